// round 5
// baseline (speedup 1.0000x reference)
#include <cuda_runtime.h>
#include <cuda_fp16.h>

#define BB 256
#define SS 512
#define FF 64
#define HH 128
#define NT 512

// g_wk[gate][kp][j] = half2(W[FF+2kp][j], W[FF+2kp+1][j]) ; gates 0..3 = i,f,o,g
__device__ __align__(16) __half2 g_wk[4 * 64 * 128];
__device__ __align__(16) float2  g_xw2[2 * 64 * 128];   // [p][k][j] = (w_g(2p), w_g(2p+1))
__device__ __align__(16) float2  g_bias2[2 * 128];

__global__ void pack_kernel(const float* __restrict__ Wi, const float* __restrict__ bi,
                            const float* __restrict__ Wf, const float* __restrict__ bf,
                            const float* __restrict__ Wo, const float* __restrict__ bo,
                            const float* __restrict__ Wg, const float* __restrict__ bg) {
    const int kp = blockIdx.x;     // 0..63
    const int j  = threadIdx.x;    // 0..127
    const int d0 = FF + 2 * kp, d1 = d0 + 1;
    g_wk[0 * 8192 + kp * 128 + j] = __floats2half2_rn(Wi[d0 * HH + j], Wi[d1 * HH + j]);
    g_wk[1 * 8192 + kp * 128 + j] = __floats2half2_rn(Wf[d0 * HH + j], Wf[d1 * HH + j]);
    g_wk[2 * 8192 + kp * 128 + j] = __floats2half2_rn(Wo[d0 * HH + j], Wo[d1 * HH + j]);
    g_wk[3 * 8192 + kp * 128 + j] = __floats2half2_rn(Wg[d0 * HH + j], Wg[d1 * HH + j]);
    g_xw2[0 * 8192 + kp * 128 + j] = make_float2(Wi[kp * HH + j], Wf[kp * HH + j]);
    g_xw2[1 * 8192 + kp * 128 + j] = make_float2(Wo[kp * HH + j], Wg[kp * HH + j]);
    if (kp == 0) {
        g_bias2[j]       = make_float2(bi[j], bf[j]);
        g_bias2[128 + j] = make_float2(bo[j], bg[j]);
    }
}

__device__ __forceinline__ float fast_ex2(float a) { float r; asm("ex2.approx.f32 %0, %1;" : "=f"(r) : "f"(a)); return r; }
__device__ __forceinline__ float fast_rcp(float a) { float r; asm("rcp.approx.f32 %0, %1;" : "=f"(r) : "f"(a)); return r; }
__device__ __forceinline__ float tanh_ex(float x) { return fmaf(-2.0f, fast_rcp(1.0f + fast_ex2(2.8853900817779268f * x)), 1.0f); }

__device__ __forceinline__ __half2 u2h2(unsigned u) { __half2 r; *reinterpret_cast<unsigned*>(&r) = u; return r; }
__device__ __forceinline__ unsigned h2u(__half2 h) { return *reinterpret_cast<unsigned*>(&h); }
__device__ __forceinline__ __half2 tanh_h2(__half2 a) {
    unsigned r, x = h2u(a);
    asm("tanh.approx.f16x2 %0, %1;" : "=r"(r) : "r"(x));
    return u2h2(r);
}
__device__ __forceinline__ __half2 pairsum(__half2 a, __half2 b) {
    const unsigned lo = __byte_perm(h2u(a), h2u(b), 0x5410);
    const unsigned hi = __byte_perm(h2u(a), h2u(b), 0x7632);
    return __hadd2(u2h2(lo), u2h2(hi));
}
__device__ __forceinline__ __half2 red4(const __half2* a) {
    return __hadd2(__hadd2(a[0], a[1]), __hadd2(a[2], a[3]));
}

// Smem: [0,131072) float2 s_xw | [131072,132160) half s_h16[2 buf][2 b stride 136] | [132160,+512) s_x
#define SMH_OFF 131072
#define SX_OFF  132160
#define SMEM_BYTES (132160 + 512)

__global__ void __launch_bounds__(NT, 1)
clstm_kernel(const float* __restrict__ x, const float* __restrict__ td, float* __restrict__ out) {
    extern __shared__ char sm[];
    float2* s_xw  = reinterpret_cast<float2*>(sm);
    __half* s_h16 = reinterpret_cast<__half*>(sm + SMH_OFF);
    float*  s_x   = reinterpret_cast<float*>(sm + SX_OFF);

    const int t    = threadIdx.x;
    const int lane = t & 31;
    const int jj   = ((t >> 5) << 3) | (lane & 7);   // 0..127
    const int p    = (lane >> 3) & 1;                // 0: gates(i,f), owns c ; 1: gates(o,g), owns h
    const int ks   = (lane >> 4) & 1;                // k-half
    const int b0   = blockIdx.x * 2;

    // Weights: 2 gates x 32 k-pairs (own k-half). 64 regs.
    __half2 wA[32], wB[32];
#pragma unroll
    for (int q = 0; q < 32; q++) {
        const int kp = ks * 32 + q;
        wA[q] = g_wk[(2 * p) * 8192 + kp * 128 + jj];
        wB[q] = g_wk[(2 * p + 1) * 8192 + kp * 128 + jj];
    }
#pragma unroll 4
    for (int i = t; i < 2 * FF * 128; i += NT) s_xw[i] = g_xw2[i];
    const float2 biasv = g_bias2[p * 128 + jj];

    // activation constants per p:  p0: sigmoid,sigmoid ; p1: sigmoid(o), tanh(g)
    const __half2 SCL = p ? __floats2half2_rn(0.5f, 1.0f) : __floats2half2_rn(0.5f, 0.5f);
    const __half2 SAD = p ? __floats2half2_rn(0.5f, 0.0f) : __floats2half2_rn(0.5f, 0.5f);

    // Per-thread state: S = stage state (c for p0, h for p1); Bs = base; tc = tanh(c) (p0)
    float S0 = 0.f, S1 = 0.f, Bs0 = 0.f, Bs1 = 0.f, tc0 = 0.f, tc1 = 0.f;
    int buf = 0;
    for (int i = t; i < 544; i += NT) s_h16[i] = __float2half_rn(0.f);
    __syncthreads();

#pragma unroll 1
    for (int sidx = 0; sidx < SS; sidx++) {
        if (t < 2 * FF)
            s_x[t] = x[(size_t)(b0 + (t >> 6)) * SS * FF + (size_t)sidx * FF + (t & 63)];
        const float dt0 = fminf(__ldg(&td[(size_t)b0 * SS + sidx]), 1.0f) * 0.25f;
        const float dt1 = fminf(__ldg(&td[(size_t)(b0 + 1) * SS + sidx]), 1.0f) * 0.25f;
        __syncthreads();

        // x-projection: own k-half, own gate-pair, both batches (fp32)
        float xp0 = 0.f, xp1 = 0.f, xp2 = 0.f, xp3 = 0.f;
#pragma unroll 8
        for (int q = 0; q < 32; q++) {
            const int k = ks * 32 + q;
            const float2 wv = s_xw[p * 8192 + k * 128 + jj];
            const float x0 = s_x[k], x1 = s_x[64 + k];
            xp0 = fmaf(x0, wv.x, xp0); xp1 = fmaf(x0, wv.y, xp1);
            xp2 = fmaf(x1, wv.x, xp2); xp3 = fmaf(x1, wv.y, xp3);
        }
        xp0 += __shfl_xor_sync(0xffffffffu, xp0, 16);
        xp1 += __shfl_xor_sync(0xffffffffu, xp1, 16);
        xp2 += __shfl_xor_sync(0xffffffffu, xp2, 16);
        xp3 += __shfl_xor_sync(0xffffffffu, xp3, 16);
        const __half2 pre0 = __floats2half2_rn(xp0 + biasv.x, xp1 + biasv.y);
        const __half2 pre1 = __floats2half2_rn(xp2 + biasv.x, xp3 + biasv.y);

#pragma unroll 1
        for (int sub = 0; sub < 4; sub++) {
            float acc0 = 0.f, acc1 = 0.f;
#pragma unroll 1
            for (int m = 0; m < 4; m++) {
                // ---- MAC: 128 HFMA2, 16 LDS.128 broadcast, fp16 chains of 8 ----
                const __half* hbuf = s_h16 + buf * 272 + ks * 64;
                const uint4* h0 = reinterpret_cast<const uint4*>(hbuf);
                const uint4* h1 = reinterpret_cast<const uint4*>(hbuf + 136);
                __half2 aA0[4], aB0[4], aA1[4], aB1[4];
                uint4 c0 = h0[0], c1 = h1[0];
#pragma unroll
                for (int r = 0; r < 8; r++) {
                    const uint4 d0 = c0, d1 = c1;
                    if (r < 7) { c0 = h0[r + 1]; c1 = h1[r + 1]; }
                    const __half2 e0[4] = {u2h2(d0.x), u2h2(d0.y), u2h2(d0.z), u2h2(d0.w)};
                    const __half2 e1[4] = {u2h2(d1.x), u2h2(d1.y), u2h2(d1.z), u2h2(d1.w)};
#pragma unroll
                    for (int q = 0; q < 4; q++) {
                        const int kp = r * 4 + q;
                        if (r == 0) {
                            aA0[q] = __hmul2(e0[q], wA[kp]);
                            aB0[q] = __hmul2(e0[q], wB[kp]);
                            aA1[q] = __hmul2(e1[q], wA[kp]);
                            aB1[q] = __hmul2(e1[q], wB[kp]);
                        } else {
                            aA0[q] = __hfma2(e0[q], wA[kp], aA0[q]);
                            aB0[q] = __hfma2(e0[q], wB[kp], aB0[q]);
                            aA1[q] = __hfma2(e1[q], wA[kp], aA1[q]);
                            aB1[q] = __hfma2(e1[q], wB[kp], aB1[q]);
                        }
                    }
                }
                // reduce -> half2(zA, zB) per batch (own ks partial), combine ks, add pre
                __half2 z0 = pairsum(red4(aA0), red4(aB0));
                __half2 z1 = pairsum(red4(aA1), red4(aB1));
                z0 = __hadd2(z0, u2h2(__shfl_xor_sync(0xffffffffu, h2u(z0), 16)));
                z1 = __hadd2(z1, u2h2(__shfl_xor_sync(0xffffffffu, h2u(z1), 16)));
                z0 = __hadd2(z0, pre0);
                z1 = __hadd2(z1, pre1);

                // activations: 1 f16x2 MUFU per batch
                const __half2 act0 = __hfma2(tanh_h2(__hmul2(z0, SCL)), SCL, SAD);
                const __half2 act1 = __hfma2(tanh_h2(__hmul2(z1, SCL)), SCL, SAD);

                // p-exchange: p1 sends g=(hi act0, hi act1); p0 sends tc0/tc1
                const unsigned gp = h2u(__halves2half2(__high2half(act0), __high2half(act1)));
                const unsigned r1 = __shfl_xor_sync(0xffffffffu, p ? gp : __float_as_uint(tc0), 8);
                const unsigned r2 = __shfl_xor_sync(0xffffffffu, p ? gp : __float_as_uint(tc1), 8);
                const __half2 grecv = u2h2(r1);                    // valid for p0
                const float tcr0 = __uint_as_float(r1);            // valid for p1
                const float tcr1 = __uint_as_float(r2);

                const float wm = (m == 1 || m == 2) ? 2.0f : 1.0f;
                const float bd0 = (m < 2) ? 0.5f * dt0 : dt0;
                const float bd1 = (m < 2) ? 0.5f * dt1 : dt1;

                // batch 0
                {
                    const float loa = __half2float(__low2half(act0));    // si | so
                    const float hia = __half2float(__high2half(act0));   // sf | g(own)
                    const float gf  = __half2float(__low2half(grecv));
                    const float ig  = loa * gf;                          // p0: i*g
                    const float Av  = p ? loa : hia;                     // so | sf
                    const float Bv  = p ? tcr0 : S0;                     // tanh(c) | c
                    const float Cv  = (p ? 0.f : ig) - S0;
                    const float k   = fmaf(Av, Bv, Cv);                  // dh | dc
                    acc0 = fmaf(wm, k, acc0);
                    if (m < 3) S0 = fmaf(bd0, k, Bs0);
                    else { Bs0 = fmaf(dt0 * (1.0f / 6.0f), acc0, Bs0); S0 = Bs0; }
                }
                // batch 1
                {
                    const float loa = __half2float(__low2half(act1));
                    const float hia = __half2float(__high2half(act1));
                    const float gf  = __half2float(__high2half(grecv));
                    const float ig  = loa * gf;
                    const float Av  = p ? loa : hia;
                    const float Bv  = p ? tcr1 : S1;
                    const float Cv  = (p ? 0.f : ig) - S1;
                    const float k   = fmaf(Av, Bv, Cv);
                    acc1 = fmaf(wm, k, acc1);
                    if (m < 3) S1 = fmaf(bd1, k, Bs1);
                    else { Bs1 = fmaf(dt1 * (1.0f / 6.0f), acc1, Bs1); S1 = Bs1; }
                }

                if (p) {   // publish h for both batches (both ks copies write same value)
                    s_h16[(buf ^ 1) * 272 + jj]       = __float2half_rn(S0);
                    s_h16[(buf ^ 1) * 272 + 136 + jj] = __float2half_rn(S1);
                } else {   // tanh(c) for next eval, fp32 exact path
                    tc0 = tanh_ex(S0);
                    tc1 = tanh_ex(S1);
                }
                buf ^= 1;
                __syncthreads();
            }
        }
        if (p && ks == 0) {
            out[(size_t)b0 * SS * HH + (size_t)sidx * HH + jj]       = Bs0;
            out[(size_t)(b0 + 1) * SS * HH + (size_t)sidx * HH + jj] = Bs1;
        }
    }
}

extern "C" void kernel_launch(void* const* d_in, const int* in_sizes, int n_in,
                              void* d_out, int out_size) {
    const float* x  = (const float*)d_in[0];
    const float* td = (const float*)d_in[1];
    const float* Wi = (const float*)d_in[2];
    const float* bi = (const float*)d_in[3];
    const float* Wf = (const float*)d_in[4];
    const float* bf = (const float*)d_in[5];
    const float* Wo = (const float*)d_in[6];
    const float* bo = (const float*)d_in[7];
    const float* Wg = (const float*)d_in[8];
    const float* bg = (const float*)d_in[9];
    float* out = (float*)d_out;

    cudaFuncSetAttribute(clstm_kernel, cudaFuncAttributeMaxDynamicSharedMemorySize, SMEM_BYTES);

    pack_kernel<<<64, 128>>>(Wi, bi, Wf, bf, Wo, bo, Wg, bg);
    clstm_kernel<<<BB / 2, NT, SMEM_BYTES>>>(x, td, out);
}

// round 6
// speedup vs baseline: 1.2160x; 1.2160x over previous
#include <cuda_runtime.h>
#include <cuda_fp16.h>

#define BB 256
#define SS 512
#define FF 64
#define HH 128
#define NT 256

// Weights packed along k: g_wk[gate][kp][j] = half2(W[FF+2kp][j], W[FF+2kp+1][j])
__device__ __align__(16) __half2 g_wk[4 * 64 * 128];
__device__ __align__(16) float4  g_xw4[64 * 128];    // (xk,j) -> (wi,wf,wo,wg)
__device__ __align__(16) float4  g_bias4[128];

__global__ void pack_kernel(const float* __restrict__ Wi, const float* __restrict__ bi,
                            const float* __restrict__ Wf, const float* __restrict__ bf,
                            const float* __restrict__ Wo, const float* __restrict__ bo,
                            const float* __restrict__ Wg, const float* __restrict__ bg) {
    const int kp = blockIdx.x;       // 0..63 (k-pair)
    const int t  = threadIdx.x;
    const int j  = t & 127;
    const int pr = t >> 7;
    const int d0 = FF + 2 * kp, d1 = FF + 2 * kp + 1;
    if (pr == 0) {
        g_wk[0 * 8192 + kp * 128 + j] = __floats2half2_rn(Wi[d0 * HH + j], Wi[d1 * HH + j]);
        g_wk[1 * 8192 + kp * 128 + j] = __floats2half2_rn(Wf[d0 * HH + j], Wf[d1 * HH + j]);
        g_xw4[kp * 128 + j] = make_float4(Wi[kp * HH + j], Wf[kp * HH + j],
                                          Wo[kp * HH + j], Wg[kp * HH + j]);
    } else {
        g_wk[2 * 8192 + kp * 128 + j] = __floats2half2_rn(Wo[d0 * HH + j], Wo[d1 * HH + j]);
        g_wk[3 * 8192 + kp * 128 + j] = __floats2half2_rn(Wg[d0 * HH + j], Wg[d1 * HH + j]);
        if (kp == 0) g_bias4[j] = make_float4(bi[j], bf[j], bo[j], bg[j]);
    }
}

__device__ __forceinline__ float fast_ex2(float a) { float r; asm("ex2.approx.f32 %0, %1;" : "=f"(r) : "f"(a)); return r; }
__device__ __forceinline__ float fast_rcp(float a) { float r; asm("rcp.approx.f32 %0, %1;" : "=f"(r) : "f"(a)); return r; }
__device__ __forceinline__ float tanh_ex(float x) { return fmaf(-2.0f, fast_rcp(1.0f + fast_ex2(2.8853900817779268f * x)), 1.0f); }

__device__ __forceinline__ __half2 u2h2(unsigned u) { __half2 r; *reinterpret_cast<unsigned*>(&r) = u; return r; }
__device__ __forceinline__ unsigned h2u(__half2 h) { return *reinterpret_cast<unsigned*>(&h); }
__device__ __forceinline__ __half2 tanh_h2(__half2 a) {
    unsigned r, x = h2u(a);
    asm("tanh.approx.f16x2 %0, %1;" : "=r"(r) : "r"(x));
    return u2h2(r);
}
__device__ __forceinline__ __half2 pairsum(__half2 a, __half2 b) {
    const unsigned lo = __byte_perm(h2u(a), h2u(b), 0x5410);
    const unsigned hi = __byte_perm(h2u(a), h2u(b), 0x7632);
    return __hadd2(u2h2(lo), u2h2(hi));
}
__device__ __forceinline__ __half2 red4(const __half2* a) {
    return __hadd2(__hadd2(a[0], a[1]), __hadd2(a[2], a[3]));
}

// Smem: [0,131072) float4 s_xw | [131072,+1088) half s_h16[2 buf][2 b stride 136] | s_x
#define SMH_OFF 131072
#define SX_OFF  132160
#define SMEM_BYTES (132160 + 512)

__global__ void __launch_bounds__(NT, 1)
clstm_kernel(const float* __restrict__ x, const float* __restrict__ td, float* __restrict__ out) {
    extern __shared__ char sm[];
    float4* s_xw  = reinterpret_cast<float4*>(sm);
    __half* s_h16 = reinterpret_cast<__half*>(sm + SMH_OFF);
    float*  s_x   = reinterpret_cast<float*>(sm + SX_OFF);

    const int t    = threadIdx.x;
    const int lane = t & 31;
    const int j    = ((t >> 5) << 4) | (lane & 15);
    const int ks   = (lane >> 4) & 1;          // k-half AND batch owner
    const int b0   = blockIdx.x * 2;
    const int batch = b0 + ks;

    // Weights: 4 gates x 32 k-pairs (own k-half). 128 regs, shared across both batches.
    __half2 wi[32], wf[32], wo[32], wg[32];
#pragma unroll
    for (int q = 0; q < 32; q++) {
        const int kp = ks * 32 + q;
        wi[q] = g_wk[0 * 8192 + kp * 128 + j];
        wf[q] = g_wk[1 * 8192 + kp * 128 + j];
        wo[q] = g_wk[2 * 8192 + kp * 128 + j];
        wg[q] = g_wk[3 * 8192 + kp * 128 + j];
    }
#pragma unroll 4
    for (int i = t; i < FF * 128; i += NT) s_xw[i] = g_xw4[i];
    const float4 bias4 = g_bias4[j];
    const float biasA[4] = {bias4.x, bias4.y, bias4.z, bias4.w};

    const __half2 H_HALF = __floats2half2_rn(0.5f, 0.5f);
    const __half2 H_SM   = __floats2half2_rn(0.5f, 1.0f);
    const __half2 H_SB   = __floats2half2_rn(0.5f, 0.0f);

    float hB = 0.f, cB = 0.f, hS = 0.f, cS = 0.f;
    int buf = 0;
    s_h16[t] = __float2half_rn(0.f);
    if (t < 16) s_h16[256 + t] = __float2half_rn(0.f);
    __syncthreads();

#pragma unroll 1
    for (int sidx = 0; sidx < SS; sidx++) {
        if (t < 2 * FF)
            s_x[t] = x[(size_t)(b0 + (t >> 6)) * SS * FF + (size_t)sidx * FF + (t & 63)];
        const float dt  = fminf(__ldg(&td[(size_t)batch * SS + sidx]), 1.0f) * 0.25f;
        const float dth = 0.5f * dt, dt6 = dt * (1.0f / 6.0f);
        __syncthreads();

        // pre = bias + x_t @ W_x (fp32, hoisted over all 16 evals)
        float xpa[4] = {0.f, 0.f, 0.f, 0.f}, xpb[4] = {0.f, 0.f, 0.f, 0.f};
#pragma unroll 8
        for (int q = 0; q < 32; q++) {
            const int kk = ks * 32 + q;
            const float4 wv = s_xw[kk * 128 + j];
            const float x0 = s_x[kk], x1 = s_x[64 + kk];
            xpa[0] = fmaf(x0, wv.x, xpa[0]); xpa[1] = fmaf(x0, wv.y, xpa[1]);
            xpa[2] = fmaf(x0, wv.z, xpa[2]); xpa[3] = fmaf(x0, wv.w, xpa[3]);
            xpb[0] = fmaf(x1, wv.x, xpb[0]); xpb[1] = fmaf(x1, wv.y, xpb[1]);
            xpb[2] = fmaf(x1, wv.z, xpb[2]); xpb[3] = fmaf(x1, wv.w, xpb[3]);
        }
        float pre[4];
#pragma unroll
        for (int g = 0; g < 4; g++) {
            const float mine = ks ? xpb[g] : xpa[g];
            const float oth  = ks ? xpa[g] : xpb[g];
            pre[g] = biasA[g] + mine + __shfl_xor_sync(0xffffffffu, oth, 16);
        }
        const __half2 pre_if = __floats2half2_rn(pre[0], pre[1]);
        const __half2 pre_og = __floats2half2_rn(pre[2], pre[3]);

#pragma unroll 1
        for (int sub = 0; sub < 4; sub++) {
            float accH = 0.f, accC = 0.f;
#pragma unroll 1
            for (int m = 0; m < 4; m++) {
                // tanh(c) of carried stage state: issued first, hides under MAC issue.
                const float tcs = tanh_ex(cS);

                const __half* hb = s_h16 + buf * 272;
                const uint4* hpo = reinterpret_cast<const uint4*>(hb) + 25 * ks;        // own batch
                const uint4* hpx = reinterpret_cast<const uint4*>(hb) + (17 - 9 * ks);  // other batch

                // ---- Phase A: OTHER batch partial (128 HFMA2), reduce, shfl EARLY ----
                __half2 aXi[4], aXf[4], aXo[4], aXg[4];
                uint4 px = hpx[0];
#pragma unroll
                for (int r = 0; r < 8; r++) {
                    const uint4 cx = px;
                    if (r < 7) px = hpx[r + 1];
                    const __half2 e[4] = {u2h2(cx.x), u2h2(cx.y), u2h2(cx.z), u2h2(cx.w)};
#pragma unroll
                    for (int q = 0; q < 4; q++) {
                        const int kp = r * 4 + q;
                        if (r == 0) {
                            aXi[q] = __hmul2(e[q], wi[kp]);
                            aXf[q] = __hmul2(e[q], wf[kp]);
                            aXo[q] = __hmul2(e[q], wo[kp]);
                            aXg[q] = __hmul2(e[q], wg[kp]);
                        } else {
                            aXi[q] = __hfma2(e[q], wi[kp], aXi[q]);
                            aXf[q] = __hfma2(e[q], wf[kp], aXf[q]);
                            aXo[q] = __hfma2(e[q], wo[kp], aXo[q]);
                            aXg[q] = __hfma2(e[q], wg[kp], aXg[q]);
                        }
                    }
                }
                const __half2 tif_x = pairsum(red4(aXi), red4(aXf));
                const __half2 tog_x = pairsum(red4(aXo), red4(aXg));
                const unsigned e_if = __shfl_xor_sync(0xffffffffu, h2u(tif_x), 16);
                const unsigned e_og = __shfl_xor_sync(0xffffffffu, h2u(tog_x), 16);

                // ---- Phase B: OWN batch partial (128 HFMA2) — shfl latency hides here ----
                __half2 aOi[4], aOf[4], aOo[4], aOg[4];
                uint4 po = hpo[0];
#pragma unroll
                for (int r = 0; r < 8; r++) {
                    const uint4 co = po;
                    if (r < 7) po = hpo[r + 1];
                    const __half2 e[4] = {u2h2(co.x), u2h2(co.y), u2h2(co.z), u2h2(co.w)};
#pragma unroll
                    for (int q = 0; q < 4; q++) {
                        const int kp = r * 4 + q;
                        if (r == 0) {
                            aOi[q] = __hmul2(e[q], wi[kp]);
                            aOf[q] = __hmul2(e[q], wf[kp]);
                            aOo[q] = __hmul2(e[q], wo[kp]);
                            aOg[q] = __hmul2(e[q], wg[kp]);
                        } else {
                            aOi[q] = __hfma2(e[q], wi[kp], aOi[q]);
                            aOf[q] = __hfma2(e[q], wf[kp], aOf[q]);
                            aOo[q] = __hfma2(e[q], wo[kp], aOo[q]);
                            aOg[q] = __hfma2(e[q], wg[kp], aOg[q]);
                        }
                    }
                }
                const __half2 tif_o = pairsum(red4(aOi), red4(aOf));
                const __half2 tog_o = pairsum(red4(aOo), red4(aOg));

                const __half2 z_if = __hadd2(__hadd2(pre_if, tif_o), u2h2(e_if));
                const __half2 z_og = __hadd2(__hadd2(pre_og, tog_o), u2h2(e_og));

                // activations: 2 f16x2 MUFU
                const __half2 s_if = __hfma2(tanh_h2(__hmul2(z_if, H_HALF)), H_HALF, H_HALF);
                const __half2 s_og = __hfma2(tanh_h2(__hmul2(z_og, H_SM)), H_SM, H_SB);

                const __half2 g2 = __high2half2(s_og);
                const __half2 m2 = __hmul2(s_if, g2);             // (i*g, f*g)
                const float ig = __half2float(__low2half(m2));
                const float sf = __half2float(__high2half(s_if));
                const float so = __half2float(__low2half(s_og));

                const float kH = fmaf(so, tcs, -hS);              // dh = o*tanh(c) - h
                const float kC = fmaf(sf, cS, ig - cS);           // dc = i*g + (f-1)*c
                const float wm = (m == 1 || m == 2) ? 2.0f : 1.0f;
                accH = fmaf(wm, kH, accH);
                accC = fmaf(wm, kC, accC);
                if (m < 3) {
                    const float bd = (m < 2) ? dth : dt;
                    hS = fmaf(bd, kH, hB);
                    cS = fmaf(bd, kC, cB);
                } else {
                    hB = fmaf(dt6, accH, hB);
                    cB = fmaf(dt6, accC, cB);
                    hS = hB; cS = cB;
                }
                s_h16[(buf ^ 1) * 272 + ks * 136 + j] = __float2half_rn(hS);
                buf ^= 1;
                __syncthreads();
            }
        }
        out[(size_t)batch * SS * HH + (size_t)sidx * HH + j] = hB;
    }
}

extern "C" void kernel_launch(void* const* d_in, const int* in_sizes, int n_in,
                              void* d_out, int out_size) {
    const float* x  = (const float*)d_in[0];
    const float* td = (const float*)d_in[1];
    const float* Wi = (const float*)d_in[2];
    const float* bi = (const float*)d_in[3];
    const float* Wf = (const float*)d_in[4];
    const float* bf = (const float*)d_in[5];
    const float* Wo = (const float*)d_in[6];
    const float* bo = (const float*)d_in[7];
    const float* Wg = (const float*)d_in[8];
    const float* bg = (const float*)d_in[9];
    float* out = (float*)d_out;

    cudaFuncSetAttribute(clstm_kernel, cudaFuncAttributeMaxDynamicSharedMemorySize, SMEM_BYTES);

    pack_kernel<<<64, NT>>>(Wi, bi, Wf, bf, Wo, bo, Wg, bg);
    clstm_kernel<<<BB / 2, NT, SMEM_BYTES>>>(x, td, out);
}